// round 5
// baseline (speedup 1.0000x reference)
#include <cuda_runtime.h>
#include <math.h>

#define T_STEPS 512
#define BATCH   128
#define IN_DIM  544
#define HID     512
#define G4H     2048
#define NACT    19
#define NBLK    128
#define NTHR    128     // thread = one batch element; block = 4 hidden units

// ---------------- scratch ----------------------------------------------------
__device__ float g_pre0[(size_t)T_STEPS * G4H * BATCH];     // [t][n][b] transposed
__device__ float g_hidden[(size_t)T_STEPS * BATCH * HID];
__device__ float g_h0[2][BATCH][HID];
__device__ float g_h1[2][BATCH][HID];
__device__ unsigned int g_bar_count;
__device__ unsigned int g_bar_release;

// ---------------- f32x2 helpers ----------------------------------------------
__device__ __forceinline__ void ffma2(unsigned long long& d, unsigned long long a,
                                      unsigned long long b) {
    asm("fma.rn.f32x2 %0, %1, %2, %0;" : "+l"(d) : "l"(a), "l"(b));
}
__device__ __forceinline__ unsigned long long dupf(float a) {
    unsigned long long r; asm("mov.b64 %0, {%1, %1};" : "=l"(r) : "f"(a)); return r;
}
__device__ __forceinline__ float2 unpk(unsigned long long v) {
    float2 r; asm("mov.b64 {%0, %1}, %2;" : "=f"(r.x), "=f"(r.y) : "l"(v)); return r;
}

// ---------------- init -------------------------------------------------------
__global__ void init_kernel(const float* __restrict__ h0) {
    if (blockIdx.x == 0 && threadIdx.x == 0) { g_bar_count = 0u; g_bar_release = 0u; }
    const int n = BATCH * HID;
    for (int i = blockIdx.x * blockDim.x + threadIdx.x; i < n; i += gridDim.x * blockDim.x) {
        (&g_h0[0][0][0])[i] = h0[i];
        (&g_h1[0][0][0])[i] = h0[n + i];
    }
}

// ---------------- precompute GEMM (f32x2) ------------------------------------
// g_pre0[t][n][b] = sum_k X[t*128+b, k] * W_ih0[n, k] + b_ih0[n] + b_hh0[n]
__global__ void __launch_bounds__(256)
pre_gemm_kernel(const float* __restrict__ X, const float* __restrict__ W,
                const float* __restrict__ bA, const float* __restrict__ bB)
{
    __shared__ float Xs[16][68];
    __shared__ float Ws[16][68];
    __shared__ float Ts[64 * 68];
    const int tid = threadIdx.x;
    const int bn  = blockIdx.x * 64;
    const int bm  = blockIdx.y * 64;
    const int tx  = tid & 15;
    const int ty  = tid >> 4;
    const int lm  = tid >> 2;
    const int lk  = (tid & 3) << 2;

    unsigned long long acc2[4][2];
#pragma unroll
    for (int i = 0; i < 4; i++) { acc2[i][0] = 0ull; acc2[i][1] = 0ull; }

    for (int k0 = 0; k0 < IN_DIM; k0 += 16) {
        float4 xa = *(const float4*)&X[(size_t)(bm + lm) * IN_DIM + k0 + lk];
        float4 wa = *(const float4*)&W[(size_t)(bn + lm) * IN_DIM + k0 + lk];
        __syncthreads();
        Xs[lk + 0][lm] = xa.x; Xs[lk + 1][lm] = xa.y; Xs[lk + 2][lm] = xa.z; Xs[lk + 3][lm] = xa.w;
        Ws[lk + 0][lm] = wa.x; Ws[lk + 1][lm] = wa.y; Ws[lk + 2][lm] = wa.z; Ws[lk + 3][lm] = wa.w;
        __syncthreads();
#pragma unroll
        for (int k = 0; k < 16; k++) {
            float4 av = *(const float4*)&Xs[k][ty << 2];
            ulonglong2 bv = *(const ulonglong2*)&Ws[k][tx << 2];
            unsigned long long a0 = dupf(av.x), a1 = dupf(av.y), a2 = dupf(av.z), a3 = dupf(av.w);
            ffma2(acc2[0][0], a0, bv.x); ffma2(acc2[0][1], a0, bv.y);
            ffma2(acc2[1][0], a1, bv.x); ffma2(acc2[1][1], a1, bv.y);
            ffma2(acc2[2][0], a2, bv.x); ffma2(acc2[2][1], a2, bv.y);
            ffma2(acc2[3][0], a3, bv.x); ffma2(acc2[3][1], a3, bv.y);
        }
    }

    float bb[4];
#pragma unroll
    for (int j = 0; j < 4; j++) { int n = bn + (tx << 2) + j; bb[j] = bA[n] + bB[n]; }

    __syncthreads();
#pragma unroll
    for (int i = 0; i < 4; i++) {
        float2 v01 = unpk(acc2[i][0]);
        float2 v23 = unpk(acc2[i][1]);
        int ml = (ty << 2) + i;
        Ts[((tx << 2) + 0) * 68 + ml] = v01.x + bb[0];
        Ts[((tx << 2) + 1) * 68 + ml] = v01.y + bb[1];
        Ts[((tx << 2) + 2) * 68 + ml] = v23.x + bb[2];
        Ts[((tx << 2) + 3) * 68 + ml] = v23.y + bb[3];
    }
    __syncthreads();

    const int tt = bm >> 7;            // time index
    const int b0 = bm & 127;           // batch base (0 or 64)
    const int nl = tid >> 2;
    const int mq = (tid & 3) << 4;
    float* dst = &g_pre0[((size_t)tt * G4H + bn + nl) * BATCH + b0 + mq];
    const float* src = &Ts[nl * 68 + mq];
#pragma unroll
    for (int s = 0; s < 4; s++)
        ((float4*)dst)[s] = ((const float4*)src)[s];
}

// ---------------- persistent LSTM --------------------------------------------
__device__ __forceinline__ float sigmoidf_(float x) { return 1.f / (1.f + expf(-x)); }

__device__ __forceinline__ void grid_bar(unsigned int phase) {
    __threadfence();
    __syncthreads();
    if (threadIdx.x == 0) {
        unsigned int arrived = atomicAdd(&g_bar_count, 1u) + 1u;
        if (arrived == (unsigned)NBLK * phase) {
            atomicExch(&g_bar_release, phase);
        } else {
            while (*(volatile unsigned int*)&g_bar_release < phase) { __nanosleep(64); }
        }
    }
    __syncthreads();
}

// acc2[r] += sum_k h[b,k] * Wrows[r][k]   for r = 0..15 (4 gates x 4 units)
// Thread's own batch row only; W rows broadcast from SMEM (uniform address).
template <bool USE_MASK>
__device__ __forceinline__ void accum_K(unsigned long long* __restrict__ acc2,
                                        const float* __restrict__ hsrc,
                                        const float* __restrict__ Wb,
                                        const float* __restrict__ msm,
                                        float* __restrict__ hbuf,
                                        const int tid)
{
    const float* hb = &hbuf[tid * 132];
    for (int kc = 0; kc < 4; kc++) {
        const int k0 = kc << 7;
        __syncthreads();
#pragma unroll 4
        for (int it = 0; it < 32; it++) {
            const int idx = (it << 7) + tid;
            const int bl  = idx >> 5;
            const int kq  = (idx & 31) << 2;
            float4 v = __ldcg((const float4*)&hsrc[bl * HID + k0 + kq]);
            if (USE_MASK) { float m = msm[bl]; v.x *= m; v.y *= m; v.z *= m; v.w *= m; }
            *(float4*)&hbuf[bl * 132 + kq] = v;
        }
        __syncthreads();
#pragma unroll 2
        for (int k = 0; k < 128; k += 8) {
            ulonglong2 ha = *(const ulonglong2*)(hb + k);
            ulonglong2 hc = *(const ulonglong2*)(hb + k + 4);
#pragma unroll
            for (int r = 0; r < 16; r += 2) {
                ulonglong2 wa0 = *(const ulonglong2*)(Wb + (r + 0) * HID + k0 + k);
                ulonglong2 wb0 = *(const ulonglong2*)(Wb + (r + 0) * HID + k0 + k + 4);
                ulonglong2 wa1 = *(const ulonglong2*)(Wb + (r + 1) * HID + k0 + k);
                ulonglong2 wb1 = *(const ulonglong2*)(Wb + (r + 1) * HID + k0 + k + 4);
                ffma2(acc2[r + 0], ha.x, wa0.x);  ffma2(acc2[r + 1], ha.x, wa1.x);
                ffma2(acc2[r + 0], ha.y, wa0.y);  ffma2(acc2[r + 1], ha.y, wa1.y);
                ffma2(acc2[r + 0], hc.x, wb0.x);  ffma2(acc2[r + 1], hc.x, wb1.x);
                ffma2(acc2[r + 0], hc.y, wb0.y);  ffma2(acc2[r + 1], hc.y, wb1.y);
            }
        }
    }
}

__global__ void __launch_bounds__(NTHR, 1)
lstm_kernel(const int* __restrict__ done,
            const float* __restrict__ c0_in,
            const float* __restrict__ W_hh0,
            const float* __restrict__ W_ih1,
            const float* __restrict__ W_hh1,
            const float* __restrict__ b_ih1,
            const float* __restrict__ b_hh1,
            float* __restrict__ out_hT,
            float* __restrict__ out_cT)
{
    extern __shared__ float smem[];
    float* W0s  = smem;                    // 16 x 512  (row r = g*4 + unit)
    float* W1i  = W0s + 16 * HID;
    float* W1h  = W1i + 16 * HID;
    float* hbuf = W1h + 16 * HID;          // 128 x 132
    float* msm  = hbuf + 128 * 132;        // 128 masks

    const int tid = threadIdx.x;
    const int bid = blockIdx.x;
    const int b   = tid;                   // batch element this thread owns
    const int u0  = bid * 4;               // first hidden unit of this block

    // load weights: smem row r = g*4+lu  <-  global row g*HID + u0 + lu
    for (int i = tid; i < 16 * (HID / 4); i += NTHR) {
        int r = i >> 7, c4 = i & 127;
        int g = r >> 2, lu = r & 3;
        size_t grow = (size_t)g * HID + u0 + lu;
        ((float4*)W0s)[i] = ((const float4*)W_hh0)[grow * (HID / 4) + c4];
        ((float4*)W1i)[i] = ((const float4*)W_ih1)[grow * (HID / 4) + c4];
        ((float4*)W1h)[i] = ((const float4*)W_hh1)[grow * (HID / 4) + c4];
    }

    float bias1[16];
#pragma unroll
    for (int r = 0; r < 16; r++) {
        int row = (r >> 2) * HID + u0 + (r & 3);
        bias1[r] = b_ih1[row] + b_hh1[row];
    }

    float c0r[4], c1r[4];
#pragma unroll
    for (int ui = 0; ui < 4; ui++) {
        c0r[ui] = c0_in[(0 * BATCH + b) * HID + u0 + ui];
        c1r[ui] = c0_in[(1 * BATCH + b) * HID + u0 + ui];
    }

    unsigned int phase = 0;

    for (int t = 0; t < T_STEPS; t++) {
        const int p = t & 1;

        msm[tid] = 1.0f - (float)done[t * BATCH + tid];
        const float mk = 1.0f - (float)done[t * BATCH + b];

        // prefetch pre0 for this thread's 16 gate rows (hidden under accum)
        float pre[16];
        const float* pb = g_pre0 + (size_t)t * G4H * BATCH + b;
#pragma unroll
        for (int r = 0; r < 16; r++)
            pre[r] = __ldcg(&pb[(size_t)((r >> 2) * HID + u0 + (r & 3)) * BATCH]);

        // ---- layer 0 : gates = pre0 + (h0*mask) @ W_hh0^T ----
        unsigned long long acc2[16];
#pragma unroll
        for (int i = 0; i < 16; i++) acc2[i] = 0ull;
        accum_K<true>(acc2, &g_h0[p][0][0], W0s, msm, hbuf, tid);

        {
            float4 hout;
            float* ho = &hout.x;
#pragma unroll
            for (int ui = 0; ui < 4; ui++) {
                float2 vi = unpk(acc2[ 0 + ui]);
                float2 vf = unpk(acc2[ 4 + ui]);
                float2 vg = unpk(acc2[ 8 + ui]);
                float2 vo = unpk(acc2[12 + ui]);
                float ig = sigmoidf_(vi.x + vi.y + pre[ 0 + ui]);
                float fg = sigmoidf_(vf.x + vf.y + pre[ 4 + ui]);
                float gg = tanhf    (vg.x + vg.y + pre[ 8 + ui]);
                float og = sigmoidf_(vo.x + vo.y + pre[12 + ui]);
                float c  = fmaf(fg, c0r[ui] * mk, ig * gg);
                c0r[ui]  = c;
                ho[ui]   = og * tanhf(c);
            }
            *(float4*)&g_h0[p ^ 1][b][u0] = hout;
        }

        grid_bar(++phase);

        // ---- layer 1 : gates = b1 + h0_new @ W_ih1^T + (h1*mask) @ W_hh1^T ----
#pragma unroll
        for (int i = 0; i < 16; i++) acc2[i] = 0ull;
        accum_K<false>(acc2, &g_h0[p ^ 1][0][0], W1i, msm, hbuf, tid);
        accum_K<true >(acc2, &g_h1[p][0][0],     W1h, msm, hbuf, tid);

        {
            float4 hout;
            float* ho = &hout.x;
#pragma unroll
            for (int ui = 0; ui < 4; ui++) {
                float2 vi = unpk(acc2[ 0 + ui]);
                float2 vf = unpk(acc2[ 4 + ui]);
                float2 vg = unpk(acc2[ 8 + ui]);
                float2 vo = unpk(acc2[12 + ui]);
                float ig = sigmoidf_(vi.x + vi.y + bias1[ 0 + ui]);
                float fg = sigmoidf_(vf.x + vf.y + bias1[ 4 + ui]);
                float gg = tanhf    (vg.x + vg.y + bias1[ 8 + ui]);
                float og = sigmoidf_(vo.x + vo.y + bias1[12 + ui]);
                float c  = fmaf(fg, c1r[ui] * mk, ig * gg);
                c1r[ui]  = c;
                ho[ui]   = og * tanhf(c);
            }
            *(float4*)&g_h1[p ^ 1][b][u0] = hout;
            *(float4*)&g_hidden[((size_t)t * BATCH + b) * HID + u0] = hout;
        }
    }

    grid_bar(++phase);   // all blocks' final-step writes visible before copy-out

    {
        float4 v0 = make_float4(c0r[0], c0r[1], c0r[2], c0r[3]);
        float4 v1 = make_float4(c1r[0], c1r[1], c1r[2], c1r[3]);
        *(float4*)&out_cT[(0 * BATCH + b) * HID + u0] = v0;
        *(float4*)&out_cT[(1 * BATCH + b) * HID + u0] = v1;
    }
    for (int i = bid * NTHR + tid; i < BATCH * HID; i += NBLK * NTHR) {
        out_hT[i]               = __ldcg(&(&g_h0[0][0][0])[i]);
        out_hT[BATCH * HID + i] = __ldcg(&(&g_h1[0][0][0])[i]);
    }
}

// ---------------- actor/critic heads -----------------------------------------
__global__ void __launch_bounds__(256)
head_kernel(const float* __restrict__ Wa, const float* __restrict__ ba,
            const float* __restrict__ Wc, const float* __restrict__ bc,
            float* __restrict__ out)
{
    __shared__ float Ws[NACT * HID];
    __shared__ float bs[NACT];
    for (int i = threadIdx.x; i < 18 * HID; i += blockDim.x) Ws[i] = Wa[i];
    for (int i = threadIdx.x; i < HID; i += blockDim.x) Ws[18 * HID + i] = Wc[i];
    if (threadIdx.x < 18) bs[threadIdx.x] = ba[threadIdx.x];
    if (threadIdx.x == 18) bs[18] = bc[0];
    __syncthreads();

    const int warp = threadIdx.x >> 5;
    const int lane = threadIdx.x & 31;
    const size_t m = (size_t)blockIdx.x * 8 + warp;

    const float* hrow = &g_hidden[m * HID];
    float hv[16];
#pragma unroll
    for (int j = 0; j < 16; j++) hv[j] = hrow[lane + j * 32];

#pragma unroll
    for (int a = 0; a < NACT; a++) {
        float s = 0.f;
#pragma unroll
        for (int j = 0; j < 16; j++) s = fmaf(hv[j], Ws[a * HID + lane + j * 32], s);
#pragma unroll
        for (int off = 16; off > 0; off >>= 1) s += __shfl_xor_sync(0xffffffffu, s, off);
        if (lane == a) out[m * NACT + a] = s + bs[a];
    }
}

// ---------------- launch ------------------------------------------------------
extern "C" void kernel_launch(void* const* d_in, const int* in_sizes, int n_in,
                              void* d_out, int out_size)
{
    (void)in_sizes; (void)n_in; (void)out_size;
    const float* x     = (const float*)d_in[0];
    const int*   done  = (const int*)  d_in[1];
    const float* h0    = (const float*)d_in[2];
    const float* c0    = (const float*)d_in[3];
    const float* W_ih0 = (const float*)d_in[4];
    const float* W_hh0 = (const float*)d_in[5];
    const float* b_ih0 = (const float*)d_in[6];
    const float* b_hh0 = (const float*)d_in[7];
    const float* W_ih1 = (const float*)d_in[8];
    const float* W_hh1 = (const float*)d_in[9];
    const float* b_ih1 = (const float*)d_in[10];
    const float* b_hh1 = (const float*)d_in[11];
    const float* W_a   = (const float*)d_in[12];
    const float* b_a   = (const float*)d_in[13];
    const float* W_c   = (const float*)d_in[14];
    const float* b_c   = (const float*)d_in[15];

    float* out    = (float*)d_out;
    float* out_hT = out + (size_t)T_STEPS * BATCH * NACT;
    float* out_cT = out_hT + 2 * BATCH * HID;

    const int smem_bytes = (3 * 16 * HID + 128 * 132 + 128) * (int)sizeof(float); // 166,400 B
    cudaFuncSetAttribute(lstm_kernel, cudaFuncAttributeMaxDynamicSharedMemorySize, smem_bytes);

    init_kernel<<<64, 256>>>(h0);

    dim3 gg(G4H / 64, (T_STEPS * BATCH) / 64);
    pre_gemm_kernel<<<gg, 256>>>(x, W_ih0, b_ih0, b_hh0);

    lstm_kernel<<<NBLK, NTHR, smem_bytes>>>(done, c0, W_hh0, W_ih1, W_hh1,
                                            b_ih1, b_hh1, out_hT, out_cT);

    head_kernel<<<(T_STEPS * BATCH) / 8, 256>>>(W_a, b_a, W_c, b_c, out);
}